// round 6
// baseline (speedup 1.0000x reference)
#include <cuda_runtime.h>

// ---------------- problem constants ----------------
#define BB   8
#define NNd  1024
#define MMd  128
#define KKd  16
#define CCd  16
#define DPE  64
#define EEd  131072
#define NMd  (NNd*MMd)      // 131072
#define SLICE (BB*NMd)      // 1048576 floats per power slice

// ---------------- scratch (device globals; no allocs) ----------------
__device__ __align__(16) float d_feat[(size_t)KKd * SLICE];   // [K][B][N][M]  ~67MB
__device__ __align__(16) float d_x[BB*NNd*CCd];               // [8192][16]
__device__ __align__(16) float d_g[BB*NNd*CCd];               // [8192][16]
__device__ float d_gpart[BB*32];                // per-b: 16 sums + 16 sumsq
__device__ float d_bnab[BB*32];                 // per-b: 16 A (scale) + 16 B (shift)
__device__ int   d_ei64;                        // 1 if edge_index is int64-laid-out

// ---------------- f32x2 packed-math helpers ----------------
__device__ __forceinline__ void ffma2(unsigned long long& d,
                                      unsigned long long a,
                                      unsigned long long b){
    asm("fma.rn.f32x2 %0, %1, %2, %0;" : "+l"(d) : "l"(a), "l"(b));
}
__device__ __forceinline__ float2 f2unpack(unsigned long long v){
    float2 r;
    asm("mov.b64 {%0, %1}, %2;" : "=f"(r.x), "=f"(r.y) : "l"(v));
    return r;
}

// ---------------- init kernels ----------------
__global__ void copy_w_kernel(const float* __restrict__ W){
    int i = blockIdx.x * 256 + threadIdx.x;          // float4 index, 262144 total
    ((float4*)d_feat)[i] = ((const float4*)W)[i];    // feat[0] = W  (layout matches)
}

__global__ void zero_gpart_kernel(){
    d_gpart[threadIdx.x] = 0.0f;                     // 256 == BB*32
}

// Detect edge_index storage: int64 values < 2^32 have zero high words.
__global__ void detect_ei_kernel(const int* __restrict__ ei){
    int allzero = 1;
    for (int i = 0; i < 128; i++)
        if (ei[2*i + 1] != 0) { allzero = 0; break; }
    d_ei64 = allzero;
}

// ---------------- chained power GEMM:  Y = S @ X  ----------------
// tile 64x128 (full M), BK=16, 256 threads.
// Microtile 8 rows x 4 cols per thread as 4 packed row-pairs (f32x2).
// B stored DUPLICATED in smem ((v,v) pairs, SW128-swizzled rows) so the
// broadcast operand is a single LDS.64 — no dup MOVs in the inner loop.
// Register double-buffering across kk hides LDS latency.
__global__ void __launch_bounds__(256) gemm_step(const float* __restrict__ Lap, int k){
    const int b  = blockIdx.y;
    const int tm = blockIdx.x;                        // 0..15
    const float* S = Lap   + (size_t)b * NNd * NNd;
    const float* X = d_feat + (size_t)k     * SLICE + (size_t)b * NMd;
    float*       Y = d_feat + (size_t)(k+1) * SLICE + (size_t)b * NMd;

    __shared__ __align__(16) float Bs[2][16][256];   // dup'd cols, 1024B rows, swizzled
    __shared__ __align__(16) float As[2][16][68];    // k-major, padded stride (272B)

    const int t  = threadIdx.x;
    const int ci = t >> 3;             // 0..31  -> cols ci*4..+3
    const int ri = t & 7;              // 0..7   -> rows ri*8..+7

    const int ar = t >> 2;             // 0..63  A row within tile
    const int ak = (t & 3) * 4;        // 0,4,8,12
    const float* Ap = S + (size_t)(tm * 64 + ar) * NNd + ak;

    const float* Bp = X + t * 8;       // 8 consecutive floats per thread per stage
    const int kkr = t >> 4;            // B dest kk row
    const int cb  = (t & 15) * 8;      // B dest col base

    // Precomputed swizzled byte offsets (kk-invariant: kk stride is 1024B,
    // swizzle only mixes bits[9:7] -> bits[6:4] of the within-row offset).
    int bro[4], bso[4];
    #pragma unroll
    for (int j = 0; j < 4; j++){
        const int off = (ci*4 + j) * 8;            // read: dup pair of col ci*4+j
        bro[j] = off ^ (((off >> 7) & 7) << 4);
        const int so  = cb*8 + j*16;               // store: 16B chunk j
        bso[j] = so ^ (((so >> 7) & 7) << 4);
    }

    unsigned long long acc[4][4];
    #pragma unroll
    for (int i = 0; i < 4; i++)
        #pragma unroll
        for (int j = 0; j < 4; j++) acc[i][j] = 0ull;

    // ---- prologue: fill stage 0 ----
    float4 aR  = *(const float4*)(Ap);
    float4 bv0 = *(const float4*)(Bp);
    float4 bv1 = *(const float4*)(Bp + 4);
    {
        char* brc = (char*)&Bs[0][kkr][0];
        *(float4*)(brc + bso[0]) = make_float4(bv0.x, bv0.x, bv0.y, bv0.y);
        *(float4*)(brc + bso[1]) = make_float4(bv0.z, bv0.z, bv0.w, bv0.w);
        *(float4*)(brc + bso[2]) = make_float4(bv1.x, bv1.x, bv1.y, bv1.y);
        *(float4*)(brc + bso[3]) = make_float4(bv1.z, bv1.z, bv1.w, bv1.w);
        As[0][ak+0][ar] = aR.x; As[0][ak+1][ar] = aR.y;
        As[0][ak+2][ar] = aR.z; As[0][ak+3][ar] = aR.w;
    }
    __syncthreads();

    for (int it = 0; it < 64; ++it){
        const int s = it & 1;
        if (it < 63){
            const int kb = (it + 1) * 16;
            aR  = *(const float4*)(Ap + kb);
            bv0 = *(const float4*)(Bp + kb*128);
            bv1 = *(const float4*)(Bp + kb*128 + 4);
        }

        const float* arow = &As[s][0][0];
        const char*  brow = (const char*)&Bs[s][0][0];

        // register pipeline: cur regs for kk, next regs prefetched
        ulonglong2 cA0 = *(const ulonglong2*)(arow + ri*8);
        ulonglong2 cA1 = *(const ulonglong2*)(arow + ri*8 + 4);
        unsigned long long cB0 = *(const unsigned long long*)(brow + bro[0]);
        unsigned long long cB1 = *(const unsigned long long*)(brow + bro[1]);
        unsigned long long cB2 = *(const unsigned long long*)(brow + bro[2]);
        unsigned long long cB3 = *(const unsigned long long*)(brow + bro[3]);

        #pragma unroll
        for (int kk = 0; kk < 16; ++kk){
            ulonglong2 nA0, nA1;
            unsigned long long nB0, nB1, nB2, nB3;
            if (kk < 15){
                const float* ap2 = arow + (kk + 1) * 68 + ri*8;
                nA0 = *(const ulonglong2*)(ap2);
                nA1 = *(const ulonglong2*)(ap2 + 4);
                const char* bp2 = brow + (kk + 1) * 1024;
                nB0 = *(const unsigned long long*)(bp2 + bro[0]);
                nB1 = *(const unsigned long long*)(bp2 + bro[1]);
                nB2 = *(const unsigned long long*)(bp2 + bro[2]);
                nB3 = *(const unsigned long long*)(bp2 + bro[3]);
            }
            ffma2(acc[0][0], cA0.x, cB0); ffma2(acc[0][1], cA0.x, cB1);
            ffma2(acc[0][2], cA0.x, cB2); ffma2(acc[0][3], cA0.x, cB3);
            ffma2(acc[1][0], cA0.y, cB0); ffma2(acc[1][1], cA0.y, cB1);
            ffma2(acc[1][2], cA0.y, cB2); ffma2(acc[1][3], cA0.y, cB3);
            ffma2(acc[2][0], cA1.x, cB0); ffma2(acc[2][1], cA1.x, cB1);
            ffma2(acc[2][2], cA1.x, cB2); ffma2(acc[2][3], cA1.x, cB3);
            ffma2(acc[3][0], cA1.y, cB0); ffma2(acc[3][1], cA1.y, cB1);
            ffma2(acc[3][2], cA1.y, cB2); ffma2(acc[3][3], cA1.y, cB3);
            if (kk < 15){
                cA0 = nA0; cA1 = nA1;
                cB0 = nB0; cB1 = nB1; cB2 = nB2; cB3 = nB3;
            }
        }

        if (it < 63){
            const int s1 = s ^ 1;
            As[s1][ak+0][ar] = aR.x; As[s1][ak+1][ar] = aR.y;
            As[s1][ak+2][ar] = aR.z; As[s1][ak+3][ar] = aR.w;
            char* brc = (char*)&Bs[s1][kkr][0];
            *(float4*)(brc + bso[0]) = make_float4(bv0.x, bv0.x, bv0.y, bv0.y);
            *(float4*)(brc + bso[1]) = make_float4(bv0.z, bv0.z, bv0.w, bv0.w);
            *(float4*)(brc + bso[2]) = make_float4(bv1.x, bv1.x, bv1.y, bv1.y);
            *(float4*)(brc + bso[3]) = make_float4(bv1.z, bv1.z, bv1.w, bv1.w);
        }
        __syncthreads();
    }

    // epilogue: acc[rp][c] -> rows (ri*8+2rp, +1), cols ci*4+c
    #pragma unroll
    for (int rp = 0; rp < 4; rp++){
        const float2 u0 = f2unpack(acc[rp][0]);
        const float2 u1 = f2unpack(acc[rp][1]);
        const float2 u2 = f2unpack(acc[rp][2]);
        const float2 u3 = f2unpack(acc[rp][3]);
        float4 oe; oe.x = u0.x; oe.y = u1.x; oe.z = u2.x; oe.w = u3.x;
        float4 oo; oo.x = u0.y; oo.y = u1.y; oo.z = u2.y; oo.w = u3.y;
        const size_t r0 = (size_t)(tm*64 + ri*8 + 2*rp) * MMd + ci*4;
        *(float4*)&Y[r0]        = oe;
        *(float4*)&Y[r0 + MMd]  = oo;
    }
}

// ---------------- BN statistics (Σh, Σh² per (b,c)) ----------------
__global__ void __launch_bounds__(256) gram_kernel(const float* __restrict__ lin_w,
                                                   const float* __restrict__ lin_b){
    __shared__ float lw[16][16];
    __shared__ float lb[16];
    const int t = threadIdx.x;
    lw[t >> 4][t & 15] = lin_w[t];
    if (t < 16) lb[t] = lin_b[t];
    __syncthreads();

    const int b     = blockIdx.y;
    const int chunk = blockIdx.x;                 // 0..63, 2048 points each
    float s1[16], s2[16];
    #pragma unroll
    for (int c = 0; c < 16; c++){ s1[c] = 0.f; s2[c] = 0.f; }

    for (int i = 0; i < 8; i++){
        const int p = chunk * 2048 + i * 256 + t;
        float f[16];
        #pragma unroll
        for (int kk = 0; kk < 16; kk++)
            f[kk] = d_feat[((size_t)(kk * BB + b)) * NMd + p];
        #pragma unroll
        for (int c = 0; c < 16; c++){
            float h = lb[c];
            #pragma unroll
            for (int kk = 0; kk < 16; kk++) h = fmaf(f[kk], lw[kk][c], h);
            s1[c] += h;
            s2[c] = fmaf(h, h, s2[c]);
        }
    }
    #pragma unroll
    for (int c = 0; c < 16; c++){
        atomicAdd(&d_gpart[b*32 + c],      s1[c]);
        atomicAdd(&d_gpart[b*32 + 16 + c], s2[c]);
    }
}

__global__ void bn_finalize_kernel(const float* __restrict__ bn_gamma,
                                   const float* __restrict__ bn_beta){
    const int t = threadIdx.x;
    if (t >= 128) return;
    const int b = t >> 4, c = t & 15;
    const float inv  = 1.0f / (float)NMd;
    const float mean = d_gpart[b*32 + c] * inv;
    const float var  = d_gpart[b*32 + 16 + c] * inv - mean * mean;
    const float A    = bn_gamma[c] * rsqrtf(var + 1e-5f);
    d_bnab[b*32 + c]      = A;
    d_bnab[b*32 + 16 + c] = bn_beta[c] - mean * A;
}

// ---------------- BN+ReLU+mean over M -> x, g ----------------
__global__ void __launch_bounds__(128) x_kernel(const float* __restrict__ lin_w,
                                                const float* __restrict__ lin_b){
    __shared__ float lw[16][16];
    __shared__ float sA[16], sB[16], slb[16];
    __shared__ float red[128][17];
    const int t    = threadIdx.x;
    const int node = blockIdx.x;          // 0..8191
    const int b    = node >> 10;
    const int n    = node & 1023;

    lw[t >> 4][t & 15]             = lin_w[t];
    lw[(t + 128) >> 4][t & 15]     = lin_w[t + 128];
    if (t < 16){ slb[t] = lin_b[t]; sA[t] = d_bnab[b*32 + t]; sB[t] = d_bnab[b*32 + 16 + t]; }
    __syncthreads();

    float f[16];
    #pragma unroll
    for (int kk = 0; kk < 16; kk++)
        f[kk] = d_feat[((size_t)(kk * BB + b) * NNd + n) * MMd + t];

    #pragma unroll
    for (int c = 0; c < 16; c++){
        float h = slb[c];
        #pragma unroll
        for (int kk = 0; kk < 16; kk++) h = fmaf(f[kk], lw[kk][c], h);
        h = h * sA[c] + sB[c];
        red[t][c] = fmaxf(h, 0.0f);
    }
    __syncthreads();
    for (int st = 64; st > 0; st >>= 1){
        if (t < st){
            #pragma unroll
            for (int c = 0; c < 16; c++) red[t][c] += red[t + st][c];
        }
        __syncthreads();
    }
    if (t < 16){
        const float val = red[0][t] * (1.0f / 128.0f);
        d_x[node*16 + t] = val;
        d_g[node*16 + t] = val;
    }
}

// ---------------- GIN edge aggregation (handles int32 OR int64 indices) ----
__global__ void edge_kernel(const int* __restrict__ ei){
    const int e = blockIdx.x * 256 + threadIdx.x;
    if (e >= EEd) return;
    int s, d;
    if (d_ei64){
        const long long* e64 = (const long long*)ei;
        const long long sl = e64[e];
        const long long dl = e64[EEd + e];
        if ((unsigned long long)sl >= (unsigned long long)(BB*NNd)) return;
        if ((unsigned long long)dl >= (unsigned long long)(BB*NNd)) return;
        s = (int)sl; d = (int)dl;
    } else {
        s = ei[e];
        d = ei[EEd + e];
        if ((unsigned)s >= (unsigned)(BB*NNd)) return;
        if ((unsigned)d >= (unsigned)(BB*NNd)) return;
    }
    const float4* xs = (const float4*)(d_x + (size_t)s * 16);
    const float4 a = xs[0], b = xs[1], c = xs[2], dd = xs[3];
    float* gp = d_g + (size_t)d * 16;
    atomicAdd(gp + 0,  a.x);  atomicAdd(gp + 1,  a.y);
    atomicAdd(gp + 2,  a.z);  atomicAdd(gp + 3,  a.w);
    atomicAdd(gp + 4,  b.x);  atomicAdd(gp + 5,  b.y);
    atomicAdd(gp + 6,  b.z);  atomicAdd(gp + 7,  b.w);
    atomicAdd(gp + 8,  c.x);  atomicAdd(gp + 9,  c.y);
    atomicAdd(gp + 10, c.z);  atomicAdd(gp + 11, c.w);
    atomicAdd(gp + 12, dd.x); atomicAdd(gp + 13, dd.y);
    atomicAdd(gp + 14, dd.z); atomicAdd(gp + 15, dd.w);
}

// ---------------- final 2-layer MLP ----------------
__global__ void __launch_bounds__(256) mlp_kernel(const float* __restrict__ w1,
                                                  const float* __restrict__ b1,
                                                  const float* __restrict__ w2,
                                                  const float* __restrict__ b2,
                                                  float* __restrict__ out){
    __shared__ float sw1[16*64];
    __shared__ float sw2[64*64];
    __shared__ float sb1[64], sb2[64];
    __shared__ float hid[4][64];
    const int t = threadIdx.x;
    for (int i = t; i < 1024; i += 256) sw1[i] = w1[i];
    for (int i = t; i < 4096; i += 256) sw2[i] = w2[i];
    if (t < 64){ sb1[t] = b1[t]; sb2[t] = b2[t]; }
    __syncthreads();

    const int r = t >> 6, c = t & 63;
    const int row = blockIdx.x * 4 + r;
    float gg[16];
    #pragma unroll
    for (int i = 0; i < 16; i++) gg[i] = d_g[(size_t)row * 16 + i];
    float h = sb1[c];
    #pragma unroll
    for (int i = 0; i < 16; i++) h = fmaf(gg[i], sw1[i*64 + c], h);
    hid[r][c] = fmaxf(h, 0.0f);
    __syncthreads();
    float o = sb2[c];
    #pragma unroll
    for (int i = 0; i < 64; i++) o = fmaf(hid[r][i], sw2[i*64 + c], o);
    out[(size_t)row * 64 + c] = o;
}

// ---------------- launcher ----------------
// Inputs resolved by ELEMENT COUNT (robust to metadata ordering):
//   Lap 8388608 | W 1048576 | edge_index 262144 | batch 8192 (unused)
//   phi_w2 4096 | phi_w1 1024 | lin_w 256 | phi_b1/phi_b2 64 (both zero)
//   16-sized triple {lin_b, bn_gamma, bn_beta}: lin_b and bn_beta are zeros;
//   bn_gamma is the MIDDLE occurrence in both insertion and alphabetical order.
extern "C" void kernel_launch(void* const* d_in, const int* in_sizes, int n_in,
                              void* d_out, int out_size){
    const float *Lap = 0, *W = 0, *lin_w = 0;
    const float *phi_w1 = 0, *phi_w2 = 0;
    const int* ei = 0;
    const float* s16[3] = {0, 0, 0};  int n16 = 0;
    const float* s64[2] = {0, 0};     int n64 = 0;

    for (int i = 0; i < n_in; i++){
        switch (in_sizes[i]){
            case 8388608: Lap    = (const float*)d_in[i]; break;
            case 1048576: W      = (const float*)d_in[i]; break;
            case  262144: ei     = (const int*)d_in[i]; break;
            case    4096: phi_w2 = (const float*)d_in[i]; break;
            case    1024: phi_w1 = (const float*)d_in[i]; break;
            case     256: lin_w  = (const float*)d_in[i]; break;
            case      64: if (n64 < 2) s64[n64++] = (const float*)d_in[i]; break;
            case      16: if (n16 < 3) s16[n16++] = (const float*)d_in[i]; break;
            default: break; // batch (8192) unused
        }
    }
    const float* lin_b    = s16[0];
    const float* bn_gamma = s16[1];
    const float* bn_beta  = s16[2];
    const float* phi_b1   = s64[0];
    const float* phi_b2   = s64[1];
    float* out            = (float*)d_out;

    copy_w_kernel<<<1024, 256>>>(W);          // feat[0] = W
    zero_gpart_kernel<<<1, 256>>>();
    detect_ei_kernel<<<1, 1>>>(ei);

    for (int k = 0; k < KKd - 1; ++k)
        gemm_step<<<dim3(16, BB), 256>>>(Lap, k);

    gram_kernel<<<dim3(64, BB), 256>>>(lin_w, lin_b);
    bn_finalize_kernel<<<1, 128>>>(bn_gamma, bn_beta);
    x_kernel<<<BB * NNd, 128>>>(lin_w, lin_b);
    edge_kernel<<<(EEd + 255) / 256, 256>>>(ei);
    mlp_kernel<<<(BB * NNd) / 4, 256>>>(phi_w1, phi_b1, phi_w2, phi_b2, out);
}

// round 7
// speedup vs baseline: 1.6287x; 1.6287x over previous
#include <cuda_runtime.h>

// ---------------- problem constants ----------------
#define BB   8
#define NNd  1024
#define MMd  128
#define KKd  16
#define CCd  16
#define DPE  64
#define EEd  131072
#define NMd  (NNd*MMd)      // 131072
#define SLICE (BB*NMd)      // 1048576 floats per power slice

// ---------------- scratch (device globals; no allocs) ----------------
__device__ __align__(16) float d_feat[(size_t)KKd * SLICE];   // [K][B][N][M]  ~67MB
__device__ __align__(16) float d_x[BB*NNd*CCd];               // [8192][16]
__device__ __align__(16) float d_g[BB*NNd*CCd];               // [8192][16]
__device__ float d_gpart[BB*32];                // per-b: 16 sums + 16 sumsq
__device__ float d_bnab[BB*32];                 // per-b: 16 A (scale) + 16 B (shift)
__device__ int   d_ei64;                        // 1 if edge_index is int64-laid-out

// ---------------- f32x2 packed-math helpers ----------------
__device__ __forceinline__ void ffma2(unsigned long long& d,
                                      unsigned long long a,
                                      unsigned long long b){
    asm("fma.rn.f32x2 %0, %1, %2, %0;" : "+l"(d) : "l"(a), "l"(b));
}
__device__ __forceinline__ float2 f2unpack(unsigned long long v){
    float2 r;
    asm("mov.b64 {%0, %1}, %2;" : "=f"(r.x), "=f"(r.y) : "l"(v));
    return r;
}

// ---------------- init kernels ----------------
__global__ void copy_w_kernel(const float* __restrict__ W){
    int i = blockIdx.x * 256 + threadIdx.x;          // float4 index, 262144 total
    ((float4*)d_feat)[i] = ((const float4*)W)[i];    // feat[0] = W  (layout matches)
}

__global__ void zero_gpart_kernel(){
    d_gpart[threadIdx.x] = 0.0f;                     // 256 == BB*32
}

// Detect edge_index storage: int64 values < 2^32 have zero high words.
__global__ void detect_ei_kernel(const int* __restrict__ ei){
    int allzero = 1;
    for (int i = 0; i < 128; i++)
        if (ei[2*i + 1] != 0) { allzero = 0; break; }
    d_ei64 = allzero;
}

// ---------------- chained power GEMM:  Y = S @ X  ----------------
// tile 64x128 (full M), BK=16, 512 threads (16 warps/SM -> 4 warps/SMSP).
// Microtile 4 rows x 4 cols per thread: 2 packed row-pairs (f32x2) x 4 cols.
// B stored DUPLICATED ((v,v) pairs, swizzled rows): 2 adjacent dup'd cols per
// LDS.128. Per warp per kk: 3 LDS.128 + 8 FFMA2, zero MOVs, no manual reg
// pipelining (latency hidden by 4 warps/SMSP).
__global__ void __launch_bounds__(512) gemm_step(const float* __restrict__ Lap, int k){
    const int b  = blockIdx.y;
    const int tm = blockIdx.x;                        // 0..15
    const float* S = Lap   + (size_t)b * NNd * NNd;
    const float* X = d_feat + (size_t)k     * SLICE + (size_t)b * NMd;
    float*       Y = d_feat + (size_t)(k+1) * SLICE + (size_t)b * NMd;

    __shared__ __align__(16) float Bs[2][16][256];   // dup'd cols, 1024B rows, swizzled
    __shared__ __align__(16) float As[2][16][68];    // k-major, padded stride (272B)

    const int t  = threadIdx.x;
    const int ci = t >> 4;             // 0..31 -> cols ci*4..+3
    const int ri = t & 15;             // 0..15 -> rows ri*4..+3

    // A fill: thread loads float2 -> 2 scalar k-major stores
    const int ar = t >> 3;             // 0..63  A row within tile
    const int ak = (t & 7) * 2;        // 0,2,..,14
    const float* Ap = S + (size_t)(tm * 64 + ar) * NNd + ak;

    // B fill: thread loads float4 of row kkr, cols cb..cb+3
    const int kkr = t >> 5;            // 0..15
    const int cb  = (t & 31) * 4;      // 0..124
    const float* Bp = X + kkr * 128 + cb;

    // swizzled byte offsets (kk-invariant; swizzle mixes bits[9:7]->[6:4])
    int bro0 = (ci*4    ) * 8; bro0 ^= ((bro0 >> 7) & 7) << 4;  // dup cols c0,c1
    int bro1 = (ci*4 + 2) * 8; bro1 ^= ((bro1 >> 7) & 7) << 4;  // dup cols c2,c3
    int bso0 = cb*8;           bso0 ^= ((bso0 >> 7) & 7) << 4;
    int bso1 = cb*8 + 16;      bso1 ^= ((bso1 >> 7) & 7) << 4;

    unsigned long long acc[2][4];
    #pragma unroll
    for (int i = 0; i < 2; i++)
        #pragma unroll
        for (int j = 0; j < 4; j++) acc[i][j] = 0ull;

    // ---- prologue: fill stage 0 ----
    float2 aR  = *(const float2*)(Ap);
    float4 bv  = *(const float4*)(Bp);
    {
        char* brc = (char*)&Bs[0][kkr][0];
        *(float4*)(brc + bso0) = make_float4(bv.x, bv.x, bv.y, bv.y);
        *(float4*)(brc + bso1) = make_float4(bv.z, bv.z, bv.w, bv.w);
        As[0][ak+0][ar] = aR.x; As[0][ak+1][ar] = aR.y;
    }
    __syncthreads();

    for (int it = 0; it < 64; ++it){
        const int s = it & 1;
        if (it < 63){
            const int kb = (it + 1) * 16;
            aR = *(const float2*)(Ap + kb);
            bv = *(const float4*)(Bp + kb*128);
        }

        const float* arow = &As[s][0][0] + ri*4;
        const char*  brow = (const char*)&Bs[s][0][0];

        #pragma unroll
        for (int kk = 0; kk < 16; ++kk){
            const ulonglong2 Aa  = *(const ulonglong2*)(arow + kk*68);
            const ulonglong2 Bv0 = *(const ulonglong2*)(brow + kk*1024 + bro0);
            const ulonglong2 Bv1 = *(const ulonglong2*)(brow + kk*1024 + bro1);
            ffma2(acc[0][0], Aa.x, Bv0.x); ffma2(acc[0][1], Aa.x, Bv0.y);
            ffma2(acc[0][2], Aa.x, Bv1.x); ffma2(acc[0][3], Aa.x, Bv1.y);
            ffma2(acc[1][0], Aa.y, Bv0.x); ffma2(acc[1][1], Aa.y, Bv0.y);
            ffma2(acc[1][2], Aa.y, Bv1.x); ffma2(acc[1][3], Aa.y, Bv1.y);
        }

        if (it < 63){
            const int s1 = s ^ 1;
            As[s1][ak+0][ar] = aR.x; As[s1][ak+1][ar] = aR.y;
            char* brc = (char*)&Bs[s1][kkr][0];
            *(float4*)(brc + bso0) = make_float4(bv.x, bv.x, bv.y, bv.y);
            *(float4*)(brc + bso1) = make_float4(bv.z, bv.z, bv.w, bv.w);
        }
        __syncthreads();
    }

    // epilogue: acc[rp][c] -> rows (ri*4+2rp, +1), cols ci*4+c
    #pragma unroll
    for (int rp = 0; rp < 2; rp++){
        const float2 u0 = f2unpack(acc[rp][0]);
        const float2 u1 = f2unpack(acc[rp][1]);
        const float2 u2 = f2unpack(acc[rp][2]);
        const float2 u3 = f2unpack(acc[rp][3]);
        float4 oe; oe.x = u0.x; oe.y = u1.x; oe.z = u2.x; oe.w = u3.x;
        float4 oo; oo.x = u0.y; oo.y = u1.y; oo.z = u2.y; oo.w = u3.y;
        const size_t r0 = (size_t)(tm*64 + ri*4 + 2*rp) * MMd + ci*4;
        *(float4*)&Y[r0]        = oe;
        *(float4*)&Y[r0 + MMd]  = oo;
    }
}

// ---------------- BN statistics (Σh, Σh² per (b,c)) ----------------
__global__ void __launch_bounds__(256) gram_kernel(const float* __restrict__ lin_w,
                                                   const float* __restrict__ lin_b){
    __shared__ float lw[16][16];
    __shared__ float lb[16];
    const int t = threadIdx.x;
    lw[t >> 4][t & 15] = lin_w[t];
    if (t < 16) lb[t] = lin_b[t];
    __syncthreads();

    const int b     = blockIdx.y;
    const int chunk = blockIdx.x;                 // 0..31, 4096 points each
    float s1[16], s2[16];
    #pragma unroll
    for (int c = 0; c < 16; c++){ s1[c] = 0.f; s2[c] = 0.f; }

    for (int i = 0; i < 16; i++){
        const int p = chunk * 4096 + i * 256 + t;
        float f[16];
        #pragma unroll
        for (int kk = 0; kk < 16; kk++)
            f[kk] = d_feat[((size_t)(kk * BB + b)) * NMd + p];
        #pragma unroll
        for (int c = 0; c < 16; c++){
            float h = lb[c];
            #pragma unroll
            for (int kk = 0; kk < 16; kk++) h = fmaf(f[kk], lw[kk][c], h);
            s1[c] += h;
            s2[c] = fmaf(h, h, s2[c]);
        }
    }
    #pragma unroll
    for (int c = 0; c < 16; c++){
        atomicAdd(&d_gpart[b*32 + c],      s1[c]);
        atomicAdd(&d_gpart[b*32 + 16 + c], s2[c]);
    }
}

__global__ void bn_finalize_kernel(const float* __restrict__ bn_gamma,
                                   const float* __restrict__ bn_beta){
    const int t = threadIdx.x;
    if (t >= 128) return;
    const int b = t >> 4, c = t & 15;
    const float inv  = 1.0f / (float)NMd;
    const float mean = d_gpart[b*32 + c] * inv;
    const float var  = d_gpart[b*32 + 16 + c] * inv - mean * mean;
    const float A    = bn_gamma[c] * rsqrtf(var + 1e-5f);
    d_bnab[b*32 + c]      = A;
    d_bnab[b*32 + 16 + c] = bn_beta[c] - mean * A;
}

// ---------------- BN+ReLU+mean over M -> x, g ----------------
__global__ void __launch_bounds__(128) x_kernel(const float* __restrict__ lin_w,
                                                const float* __restrict__ lin_b){
    __shared__ float lw[16][16];
    __shared__ float sA[16], sB[16], slb[16];
    __shared__ float red[128][17];
    const int t    = threadIdx.x;
    const int node = blockIdx.x;          // 0..8191
    const int b    = node >> 10;
    const int n    = node & 1023;

    lw[t >> 4][t & 15]             = lin_w[t];
    lw[(t + 128) >> 4][t & 15]     = lin_w[t + 128];
    if (t < 16){ slb[t] = lin_b[t]; sA[t] = d_bnab[b*32 + t]; sB[t] = d_bnab[b*32 + 16 + t]; }
    __syncthreads();

    float f[16];
    #pragma unroll
    for (int kk = 0; kk < 16; kk++)
        f[kk] = d_feat[((size_t)(kk * BB + b) * NNd + n) * MMd + t];

    #pragma unroll
    for (int c = 0; c < 16; c++){
        float h = slb[c];
        #pragma unroll
        for (int kk = 0; kk < 16; kk++) h = fmaf(f[kk], lw[kk][c], h);
        h = h * sA[c] + sB[c];
        red[t][c] = fmaxf(h, 0.0f);
    }
    __syncthreads();
    for (int st = 64; st > 0; st >>= 1){
        if (t < st){
            #pragma unroll
            for (int c = 0; c < 16; c++) red[t][c] += red[t + st][c];
        }
        __syncthreads();
    }
    if (t < 16){
        const float val = red[0][t] * (1.0f / 128.0f);
        d_x[node*16 + t] = val;
        d_g[node*16 + t] = val;
    }
}

// ---------------- GIN edge aggregation (handles int32 OR int64 indices) ----
__global__ void edge_kernel(const int* __restrict__ ei){
    const int e = blockIdx.x * 256 + threadIdx.x;
    if (e >= EEd) return;
    int s, d;
    if (d_ei64){
        const long long* e64 = (const long long*)ei;
        const long long sl = e64[e];
        const long long dl = e64[EEd + e];
        if ((unsigned long long)sl >= (unsigned long long)(BB*NNd)) return;
        if ((unsigned long long)dl >= (unsigned long long)(BB*NNd)) return;
        s = (int)sl; d = (int)dl;
    } else {
        s = ei[e];
        d = ei[EEd + e];
        if ((unsigned)s >= (unsigned)(BB*NNd)) return;
        if ((unsigned)d >= (unsigned)(BB*NNd)) return;
    }
    const float4* xs = (const float4*)(d_x + (size_t)s * 16);
    const float4 a = xs[0], b = xs[1], c = xs[2], dd = xs[3];
    float* gp = d_g + (size_t)d * 16;
    atomicAdd(gp + 0,  a.x);  atomicAdd(gp + 1,  a.y);
    atomicAdd(gp + 2,  a.z);  atomicAdd(gp + 3,  a.w);
    atomicAdd(gp + 4,  b.x);  atomicAdd(gp + 5,  b.y);
    atomicAdd(gp + 6,  b.z);  atomicAdd(gp + 7,  b.w);
    atomicAdd(gp + 8,  c.x);  atomicAdd(gp + 9,  c.y);
    atomicAdd(gp + 10, c.z);  atomicAdd(gp + 11, c.w);
    atomicAdd(gp + 12, dd.x); atomicAdd(gp + 13, dd.y);
    atomicAdd(gp + 14, dd.z); atomicAdd(gp + 15, dd.w);
}

// ---------------- final 2-layer MLP ----------------
__global__ void __launch_bounds__(256) mlp_kernel(const float* __restrict__ w1,
                                                  const float* __restrict__ b1,
                                                  const float* __restrict__ w2,
                                                  const float* __restrict__ b2,
                                                  float* __restrict__ out){
    __shared__ float sw1[16*64];
    __shared__ float sw2[64*64];
    __shared__ float sb1[64], sb2[64];
    __shared__ float hid[4][64];
    const int t = threadIdx.x;
    for (int i = t; i < 1024; i += 256) sw1[i] = w1[i];
    for (int i = t; i < 4096; i += 256) sw2[i] = w2[i];
    if (t < 64){ sb1[t] = b1[t]; sb2[t] = b2[t]; }
    __syncthreads();

    const int r = t >> 6, c = t & 63;
    const int row = blockIdx.x * 4 + r;
    float gg[16];
    #pragma unroll
    for (int i = 0; i < 16; i++) gg[i] = d_g[(size_t)row * 16 + i];
    float h = sb1[c];
    #pragma unroll
    for (int i = 0; i < 16; i++) h = fmaf(gg[i], sw1[i*64 + c], h);
    hid[r][c] = fmaxf(h, 0.0f);
    __syncthreads();
    float o = sb2[c];
    #pragma unroll
    for (int i = 0; i < 64; i++) o = fmaf(hid[r][i], sw2[i*64 + c], o);
    out[(size_t)row * 64 + c] = o;
}

// ---------------- launcher ----------------
// Inputs resolved by ELEMENT COUNT (robust to metadata ordering):
//   Lap 8388608 | W 1048576 | edge_index 262144 | batch 8192 (unused)
//   phi_w2 4096 | phi_w1 1024 | lin_w 256 | phi_b1/phi_b2 64 (both zero)
//   16-sized triple {lin_b, bn_gamma, bn_beta}: lin_b and bn_beta are zeros;
//   bn_gamma is the MIDDLE occurrence in both insertion and alphabetical order.
extern "C" void kernel_launch(void* const* d_in, const int* in_sizes, int n_in,
                              void* d_out, int out_size){
    const float *Lap = 0, *W = 0, *lin_w = 0;
    const float *phi_w1 = 0, *phi_w2 = 0;
    const int* ei = 0;
    const float* s16[3] = {0, 0, 0};  int n16 = 0;
    const float* s64[2] = {0, 0};     int n64 = 0;

    for (int i = 0; i < n_in; i++){
        switch (in_sizes[i]){
            case 8388608: Lap    = (const float*)d_in[i]; break;
            case 1048576: W      = (const float*)d_in[i]; break;
            case  262144: ei     = (const int*)d_in[i]; break;
            case    4096: phi_w2 = (const float*)d_in[i]; break;
            case    1024: phi_w1 = (const float*)d_in[i]; break;
            case     256: lin_w  = (const float*)d_in[i]; break;
            case      64: if (n64 < 2) s64[n64++] = (const float*)d_in[i]; break;
            case      16: if (n16 < 3) s16[n16++] = (const float*)d_in[i]; break;
            default: break; // batch (8192) unused
        }
    }
    const float* lin_b    = s16[0];
    const float* bn_gamma = s16[1];
    const float* bn_beta  = s16[2];
    const float* phi_b1   = s64[0];
    const float* phi_b2   = s64[1];
    float* out            = (float*)d_out;

    copy_w_kernel<<<1024, 256>>>(W);          // feat[0] = W
    zero_gpart_kernel<<<1, 256>>>();
    detect_ei_kernel<<<1, 1>>>(ei);

    for (int k = 0; k < KKd - 1; ++k)
        gemm_step<<<dim3(16, BB), 512>>>(Lap, k);

    gram_kernel<<<dim3(32, BB), 256>>>(lin_w, lin_b);
    bn_finalize_kernel<<<1, 128>>>(bn_gamma, bn_beta);
    x_kernel<<<BB * NNd, 128>>>(lin_w, lin_b);
    edge_kernel<<<(EEd + 255) / 256, 256>>>(ei);
    mlp_kernel<<<(BB * NNd) / 4, 256>>>(phi_w1, phi_b1, phi_w2, phi_b2, out);
}